// round 1
// baseline (speedup 1.0000x reference)
#include <cuda_runtime.h>
#include <math.h>

// Problem constants
#define NTOK 4096            // B*T = 2*2048
#define DDIM 2048
#define HDIM 1408
#define NE   16              // routed experts
#define NS   2               // shared experts
#define NSLOT (NE + NS)      // 18 slots: 0..15 routed, 16..17 shared
#define TOPK 2
#define TM 128
#define TN 128
#define TK 16
// routed rows (padded per expert to TM) + shared rows (exact multiples of TM)
#define MAXROWS (NTOK*TOPK + NE*TM + NTOK*NS)   // 8192 + 2048 + 8192 = 18432
#define MAXTILESM (MAXROWS / TM)                // 144

// ---------------- device scratch (static: no allocations allowed) ------------
__device__ float g_hidden[(size_t)MAXROWS * HDIM];   // ~104 MB
__device__ int   g_row_token[MAXROWS];
__device__ float g_row_w[MAXROWS];
__device__ int   g_tile_slot[MAXTILESM];
__device__ int   g_topk_i[NTOK * TOPK];
__device__ float g_topk_w[NTOK * TOPK];
__device__ int   g_counts[NE];
__device__ int   g_fill[NE];
__device__ int   g_offsets[NSLOT];
__device__ float g_psum[NE];
__device__ float g_lsum[NE];

// ---------------- init: zero output + counters, poison row map ---------------
__global__ void init_kernel(float* __restrict__ out) {
    int idx = blockIdx.x * blockDim.x + threadIdx.x;
    int stride = gridDim.x * blockDim.x;
    for (size_t i = idx; i < (size_t)NTOK * DDIM; i += stride) out[i] = 0.0f;
    for (int i = idx; i < MAXROWS; i += stride) g_row_token[i] = -1;
    if (idx < NE) {
        g_counts[idx] = 0; g_fill[idx] = 0;
        g_psum[idx] = 0.0f; g_lsum[idx] = 0.0f;
    }
}

// ---------------- router: logits, softmax, top-2, aux-loss sums --------------
__global__ void router_kernel(const float* __restrict__ x,
                              const float* __restrict__ gw) {
    int t = blockIdx.x;
    int tid = threadIdx.x;
    float acc[NE];
#pragma unroll
    for (int e = 0; e < NE; e++) acc[e] = 0.0f;
    const float* xr = x + (size_t)t * DDIM;
    for (int d = tid; d < DDIM; d += 128) {
        float xv = xr[d];
        const float* g = gw + d * NE;
#pragma unroll
        for (int e = 0; e < NE; e++) acc[e] += xv * g[e];
    }
    __shared__ float red[128][NE + 1];
#pragma unroll
    for (int e = 0; e < NE; e++) red[tid][e] = acc[e];
    __syncthreads();
    for (int off = 64; off > 0; off >>= 1) {
        if (tid < off) {
#pragma unroll
            for (int e = 0; e < NE; e++) red[tid][e] += red[tid + off][e];
        }
        __syncthreads();
    }
    if (tid == 0) {
        float lg[NE], p[NE];
        float m = -1e30f;
#pragma unroll
        for (int e = 0; e < NE; e++) { lg[e] = red[0][e]; m = fmaxf(m, lg[e]); }
        float s = 0.0f;
#pragma unroll
        for (int e = 0; e < NE; e++) { p[e] = expf(lg[e] - m); s += p[e]; }
        float inv = 1.0f / s;
#pragma unroll
        for (int e = 0; e < NE; e++) p[e] *= inv;
        // top-2 (first index wins ties, matching jax.lax.top_k)
        int i1 = 0;
#pragma unroll
        for (int e = 1; e < NE; e++) if (p[e] > p[i1]) i1 = e;
        int i2 = (i1 == 0) ? 1 : 0;
#pragma unroll
        for (int e = 0; e < NE; e++) if (e != i1 && p[e] > p[i2]) i2 = e;
        float wsum = p[i1] + p[i2];
        g_topk_i[t * 2 + 0] = i1;
        g_topk_i[t * 2 + 1] = i2;
        g_topk_w[t * 2 + 0] = p[i1] / wsum;
        g_topk_w[t * 2 + 1] = p[i2] / wsum;
        atomicAdd(&g_counts[i1], 1);
        atomicAdd(&g_counts[i2], 1);
#pragma unroll
        for (int e = 0; e < NE; e++) {
            atomicAdd(&g_psum[e], p[e]);
            atomicAdd(&g_lsum[e], lg[e]);
        }
    }
}

// ---------------- schedule: offsets, tile->slot map, aux loss ----------------
__global__ void schedule_kernel(float* __restrict__ out, long long out_size) {
    if (threadIdx.x != 0 || blockIdx.x != 0) return;
    int tile = 0;
    for (int slot = 0; slot < NSLOT; slot++) {
        int cnt = (slot < NE) ? g_counts[slot] : NTOK;
        g_offsets[slot] = tile * TM;
        int nt = (cnt + TM - 1) / TM;
        for (int i = 0; i < nt; i++) g_tile_slot[tile++] = slot;
    }
    for (; tile < MAXTILESM; tile++) g_tile_slot[tile] = -1;
    float aux = 0.0f;
    for (int e = 0; e < NE; e++)
        aux += (g_psum[e] * (1.0f / NTOK)) * (g_lsum[e] * (1.0f / NTOK));
    aux *= (float)NE;
    if (out_size > (long long)NTOK * DDIM) out[(size_t)NTOK * DDIM] = aux;
}

// ---------------- scatter tokens into per-slot contiguous segments -----------
__global__ void scatter_kernel() {
    int i = blockIdx.x * blockDim.x + threadIdx.x;
    const int total = NTOK * TOPK + NTOK * NS;
    if (i >= total) return;
    if (i < NTOK * TOPK) {
        int e = g_topk_i[i];
        int pos = atomicAdd(&g_fill[e], 1);
        int row = g_offsets[e] + pos;
        g_row_token[row] = i >> 1;
        g_row_w[row] = g_topk_w[i];
    } else {
        int j = i - NTOK * TOPK;
        int s = j / NTOK, t = j % NTOK;
        int row = g_offsets[NE + s] + t;
        g_row_token[row] = t;
        g_row_w[row] = 1.0f;
    }
}

// ---------------- grouped FFN GEMM (fp32 SIMT, 128x128x16, 8x8/thread) -------
// PHASE1: hidden = silu(gather(x) @ W1_slot)   K=DDIM, N=HDIM
// PHASE2: out   += w_row * (hidden @ W2_slot)  K=HDIM, N=DDIM (atomicAdd)
template <bool PHASE1>
__global__ __launch_bounds__(256)
void ffn_gemm(const float* __restrict__ x,
              const float* __restrict__ sw1, const float* __restrict__ sw2,
              const float* __restrict__ ew1, const float* __restrict__ ew2,
              float* __restrict__ out) {
    int bm = blockIdx.x, bn = blockIdx.y;
    int slot = g_tile_slot[bm];
    if (slot < 0) return;
    const int KD = PHASE1 ? DDIM : HDIM;
    const int ND = PHASE1 ? HDIM : DDIM;
    const float* B;
    if (PHASE1)
        B = (slot < NE) ? ew1 + (size_t)slot * DDIM * HDIM
                        : sw1 + (size_t)(slot - NE) * DDIM * HDIM;
    else
        B = (slot < NE) ? ew2 + (size_t)slot * HDIM * DDIM
                        : sw2 + (size_t)(slot - NE) * HDIM * DDIM;
    int row0 = bm * TM;
    int tid = threadIdx.x;

    __shared__ float As[TK][TM + 4];
    __shared__ float Bs[TK][TN + 4];
    __shared__ int   s_tok[TM];
    __shared__ float s_w[TM];
    if (tid < TM) {
        s_tok[tid] = g_row_token[row0 + tid];
        s_w[tid]   = g_row_w[row0 + tid];
    }
    __syncthreads();

    float acc[8][8];
#pragma unroll
    for (int i = 0; i < 8; i++)
#pragma unroll
        for (int j = 0; j < 8; j++) acc[i][j] = 0.0f;

    int tx = tid & 15, ty = tid >> 4;

    for (int k0 = 0; k0 < KD; k0 += TK) {
        // Load A tile (gathered rows), store transposed As[k][m]
#pragma unroll
        for (int i = 0; i < 2; i++) {
            int lid = tid + i * 256;         // 0..511
            int m = lid >> 2;
            int kk = (lid & 3) << 2;
            float4 v = make_float4(0.f, 0.f, 0.f, 0.f);
            if (PHASE1) {
                int tok = s_tok[m];
                if (tok >= 0)
                    v = *(const float4*)&x[(size_t)tok * DDIM + k0 + kk];
            } else {
                v = *(const float4*)&g_hidden[(size_t)(row0 + m) * HDIM + k0 + kk];
            }
            As[kk + 0][m] = v.x; As[kk + 1][m] = v.y;
            As[kk + 2][m] = v.z; As[kk + 3][m] = v.w;
        }
        // Load B tile: B[k][n] row-major, contiguous in n
#pragma unroll
        for (int i = 0; i < 2; i++) {
            int lid = tid + i * 256;
            int k = lid >> 5;
            int nn = (lid & 31) << 2;
            *(float4*)&Bs[k][nn] =
                *(const float4*)&B[(size_t)(k0 + k) * ND + bn * TN + nn];
        }
        __syncthreads();
#pragma unroll
        for (int k = 0; k < TK; k++) {
            float a[8], b[8];
            *(float4*)&a[0] = *(const float4*)&As[k][ty * 8];
            *(float4*)&a[4] = *(const float4*)&As[k][ty * 8 + 4];
            *(float4*)&b[0] = *(const float4*)&Bs[k][tx * 8];
            *(float4*)&b[4] = *(const float4*)&Bs[k][tx * 8 + 4];
#pragma unroll
            for (int im = 0; im < 8; im++)
#pragma unroll
                for (int in = 0; in < 8; in++)
                    acc[im][in] += a[im] * b[in];
        }
        __syncthreads();
    }

    if (PHASE1) {
#pragma unroll
        for (int im = 0; im < 8; im++) {
            int row = row0 + ty * 8 + im;
            float* hp = &g_hidden[(size_t)row * HDIM + bn * TN + tx * 8];
#pragma unroll
            for (int in = 0; in < 8; in++) {
                float v = acc[im][in];
                hp[in] = v / (1.0f + __expf(-v));   // silu
            }
        }
    } else {
#pragma unroll
        for (int im = 0; im < 8; im++) {
            int m = ty * 8 + im;
            int tok = s_tok[m];
            if (tok < 0) continue;
            float w = s_w[m];
            float* op = &out[(size_t)tok * DDIM + bn * TN + tx * 8];
#pragma unroll
            for (int in = 0; in < 8; in++)
                atomicAdd(&op[in], w * acc[im][in]);
        }
    }
}

// ---------------- launch ------------------------------------------------------
extern "C" void kernel_launch(void* const* d_in, const int* in_sizes, int n_in,
                              void* d_out, int out_size) {
    const float* x   = (const float*)d_in[0];   // [2,2048,2048]
    const float* gw  = (const float*)d_in[1];   // [2048,16]
    const float* sw1 = (const float*)d_in[2];   // [2,2048,1408]
    const float* sw2 = (const float*)d_in[3];   // [2,1408,2048]
    const float* ew1 = (const float*)d_in[4];   // [16,2048,1408]
    const float* ew2 = (const float*)d_in[5];   // [16,1408,2048]
    float* out = (float*)d_out;

    init_kernel<<<1024, 256>>>(out);
    router_kernel<<<NTOK, 128>>>(x, gw);
    schedule_kernel<<<1, 32>>>(out, (long long)out_size);
    scatter_kernel<<<(NTOK * (TOPK + NS) + 255) / 256, 256>>>();

    dim3 g1(MAXTILESM, HDIM / TN);   // 144 x 11
    dim3 g2(MAXTILESM, DDIM / TN);   // 144 x 16
    ffn_gemm<true ><<<g1, 256>>>(x, sw1, sw2, ew1, ew2, out);
    ffn_gemm<false><<<g2, 256>>>(x, sw1, sw2, ew1, ew2, out);
}

// round 3
// speedup vs baseline: 2.2180x; 2.2180x over previous
#include <cuda_runtime.h>
#include <cuda_bf16.h>
#include <cstdint>
#include <math.h>

// ---------------- problem constants ----------------
#define NTOK 4096
#define DDIM 2048
#define HDIM 1408
#define NE   16
#define NS   2
#define NSLOT (NE + NS)
#define TOPK 2
#define TM 128
#define TN 128
#define KC 32
#define MAXROWS (NTOK*TOPK + NE*TM + NTOK*NS)   // 18432
#define MAXTILESM (MAXROWS / TM)                // 144

// smem tile geometry: rows of 32 bf16 + 8 pad = 80 bytes
#define PITCH 80
#define TILEB (128 * PITCH)          // 10240 B
#define OFF_TOK 0
#define OFF_W   512
#define OFF_TILES 1024
#define AHOF(b) (OFF_TILES + (b)*4*TILEB)
#define ALOF(b) (AHOF(b) + TILEB)
#define BHOF(b) (AHOF(b) + 2*TILEB)
#define BLOF(b) (AHOF(b) + 3*TILEB)
#define SMEM_BYTES (OFF_TILES + 8*TILEB)   // 82944

// ---------------- device scratch ----------------
__device__ __nv_bfloat16 g_hidden_hi[(size_t)MAXROWS * HDIM];
__device__ __nv_bfloat16 g_hidden_lo[(size_t)MAXROWS * HDIM];
__device__ int   g_row_token[MAXROWS];
__device__ float g_row_w[MAXROWS];
__device__ int   g_tile_slot[MAXTILESM];
__device__ int   g_topk_i[NTOK * TOPK];
__device__ float g_topk_w[NTOK * TOPK];
__device__ int   g_counts[NE];
__device__ int   g_fill[NE];
__device__ int   g_offsets[NSLOT];
__device__ float g_psum[NE];
__device__ float g_lsum[NE];

// ---------------- helpers ----------------
__device__ __forceinline__ uint32_t smem_u32(const void* p) {
    uint32_t a;
    asm("{ .reg .u64 t; cvta.to.shared.u64 t, %1; cvt.u32.u64 %0, t; }"
        : "=r"(a) : "l"(p));
    return a;
}
__device__ __forceinline__ void ldsm4(uint32_t* r, uint32_t addr) {
    asm volatile("ldmatrix.sync.aligned.m8n8.x4.shared.b16 {%0,%1,%2,%3}, [%4];"
                 : "=r"(r[0]), "=r"(r[1]), "=r"(r[2]), "=r"(r[3]) : "r"(addr));
}
__device__ __forceinline__ void mma16816(float* d, const uint32_t* a, const uint32_t* b) {
    asm volatile("mma.sync.aligned.m16n8k16.row.col.f32.bf16.bf16.f32 "
                 "{%0,%1,%2,%3}, {%4,%5,%6,%7}, {%8,%9}, {%0,%1,%2,%3};"
                 : "+f"(d[0]), "+f"(d[1]), "+f"(d[2]), "+f"(d[3])
                 : "r"(a[0]), "r"(a[1]), "r"(a[2]), "r"(a[3]), "r"(b[0]), "r"(b[1]));
}
__device__ __forceinline__ uint32_t pk(__nv_bfloat16 a, __nv_bfloat16 b) {
    return (uint32_t)__bfloat16_as_ushort(a) | ((uint32_t)__bfloat16_as_ushort(b) << 16);
}
__device__ __forceinline__ void split_bf(float v, __nv_bfloat16& h, __nv_bfloat16& l) {
    h = __float2bfloat16_rn(v);
    l = __float2bfloat16_rn(v - __bfloat162float(h));
}

// ---------------- init ----------------
__global__ void init_kernel(float* __restrict__ out) {
    int idx = blockIdx.x * blockDim.x + threadIdx.x;
    int stride = gridDim.x * blockDim.x;
    for (size_t i = idx; i < (size_t)NTOK * DDIM; i += stride) out[i] = 0.0f;
    for (int i = idx; i < MAXROWS; i += stride) g_row_token[i] = -1;
    if (idx < NE) {
        g_counts[idx] = 0; g_fill[idx] = 0;
        g_psum[idx] = 0.0f; g_lsum[idx] = 0.0f;
    }
}

// ---------------- router ----------------
__global__ void router_kernel(const float* __restrict__ x,
                              const float* __restrict__ gw) {
    int t = blockIdx.x;
    int tid = threadIdx.x;
    float acc[NE];
#pragma unroll
    for (int e = 0; e < NE; e++) acc[e] = 0.0f;
    const float* xr = x + (size_t)t * DDIM;
    for (int d = tid; d < DDIM; d += 128) {
        float xv = xr[d];
        const float* g = gw + d * NE;
#pragma unroll
        for (int e = 0; e < NE; e++) acc[e] += xv * g[e];
    }
    __shared__ float red[128][NE + 1];
#pragma unroll
    for (int e = 0; e < NE; e++) red[tid][e] = acc[e];
    __syncthreads();
    for (int off = 64; off > 0; off >>= 1) {
        if (tid < off) {
#pragma unroll
            for (int e = 0; e < NE; e++) red[tid][e] += red[tid + off][e];
        }
        __syncthreads();
    }
    if (tid == 0) {
        float lg[NE], p[NE];
        float m = -1e30f;
#pragma unroll
        for (int e = 0; e < NE; e++) { lg[e] = red[0][e]; m = fmaxf(m, lg[e]); }
        float s = 0.0f;
#pragma unroll
        for (int e = 0; e < NE; e++) { p[e] = expf(lg[e] - m); s += p[e]; }
        float inv = 1.0f / s;
#pragma unroll
        for (int e = 0; e < NE; e++) p[e] *= inv;
        int i1 = 0;
#pragma unroll
        for (int e = 1; e < NE; e++) if (p[e] > p[i1]) i1 = e;
        int i2 = (i1 == 0) ? 1 : 0;
#pragma unroll
        for (int e = 0; e < NE; e++) if (e != i1 && p[e] > p[i2]) i2 = e;
        float wsum = p[i1] + p[i2];
        g_topk_i[t * 2 + 0] = i1;
        g_topk_i[t * 2 + 1] = i2;
        g_topk_w[t * 2 + 0] = p[i1] / wsum;
        g_topk_w[t * 2 + 1] = p[i2] / wsum;
        atomicAdd(&g_counts[i1], 1);
        atomicAdd(&g_counts[i2], 1);
#pragma unroll
        for (int e = 0; e < NE; e++) {
            atomicAdd(&g_psum[e], p[e]);
            atomicAdd(&g_lsum[e], lg[e]);
        }
    }
}

// ---------------- schedule ----------------
__global__ void schedule_kernel(float* __restrict__ out, long long out_size) {
    if (threadIdx.x != 0 || blockIdx.x != 0) return;
    int tile = 0;
    for (int slot = 0; slot < NSLOT; slot++) {
        int cnt = (slot < NE) ? g_counts[slot] : NTOK;
        g_offsets[slot] = tile * TM;
        int nt = (cnt + TM - 1) / TM;
        for (int i = 0; i < nt; i++) g_tile_slot[tile++] = slot;
    }
    for (; tile < MAXTILESM; tile++) g_tile_slot[tile] = -1;
    float aux = 0.0f;
    for (int e = 0; e < NE; e++)
        aux += (g_psum[e] * (1.0f / NTOK)) * (g_lsum[e] * (1.0f / NTOK));
    aux *= (float)NE;
    if (out_size > (long long)NTOK * DDIM) out[(size_t)NTOK * DDIM] = aux;
}

// ---------------- scatter ----------------
__global__ void scatter_kernel() {
    int i = blockIdx.x * blockDim.x + threadIdx.x;
    const int total = NTOK * TOPK + NTOK * NS;
    if (i >= total) return;
    if (i < NTOK * TOPK) {
        int e = g_topk_i[i];
        int pos = atomicAdd(&g_fill[e], 1);
        int row = g_offsets[e] + pos;
        g_row_token[row] = i >> 1;
        g_row_w[row] = g_topk_w[i];
    } else {
        int j = i - NTOK * TOPK;
        int s = j / NTOK, t = j % NTOK;
        int row = g_offsets[NE + s] + t;
        g_row_token[row] = t;
        g_row_w[row] = 1.0f;
    }
}

// ---------------- mma.sync grouped FFN GEMM (bf16 3-term split) ----------------
// PHASE1: hidden = silu(gather(x) @ W1)   K=DDIM, N=HDIM ; hidden stored bf16 hi/lo
// PHASE2: out   += w_row * (hidden @ W2)  K=HDIM, N=DDIM (atomicAdd)
template <bool PHASE1>
__global__ __launch_bounds__(256, 2)
void ffn_mma(const float* __restrict__ x,
             const float* __restrict__ sw1, const float* __restrict__ sw2,
             const float* __restrict__ ew1, const float* __restrict__ ew2,
             float* __restrict__ out) {
    extern __shared__ char smem[];
    int bm = blockIdx.x, bn = blockIdx.y;
    int slot = g_tile_slot[bm];
    if (slot < 0) return;
    const int KD = PHASE1 ? DDIM : HDIM;
    const int ND = PHASE1 ? HDIM : DDIM;
    const int NC = KD / KC;
    const float* W;
    if (PHASE1)
        W = (slot < NE) ? ew1 + (size_t)slot * DDIM * HDIM
                        : sw1 + (size_t)(slot - NE) * DDIM * HDIM;
    else
        W = (slot < NE) ? ew2 + (size_t)slot * HDIM * DDIM
                        : sw2 + (size_t)(slot - NE) * HDIM * DDIM;
    const int row0 = bm * TM, n0 = bn * TN;
    const int tid = threadIdx.x, wid = tid >> 5, lane = tid & 31;
    int* s_tok = (int*)(smem + OFF_TOK);
    float* s_w = (float*)(smem + OFF_W);
    if (tid < TM) {
        s_tok[tid] = g_row_token[row0 + tid];
        s_w[tid]   = g_row_w[row0 + tid];
    }
    __syncthreads();

    // loader indices: A rows (2 threads/row, 16 k each), B n-cols (2 k-halves)
    const int lm  = tid >> 1;
    const int lkq = (tid & 1) * 16;
    const int lbn = tid & 127;
    const int lbk = (tid >> 7) * 16;

    const uint32_t sb = smem_u32(smem);
    const int warp_m = (wid >> 2) * 64;
    const int warp_n = (wid & 3) * 32;
    // ldmatrix lane address components
    const int a_row = warp_m + (lane & 15);
    const int a_c8  = (lane >> 4) << 3;
    const int b_row = warp_n + (lane & 7) + ((lane >> 4) << 3);
    const int b_c8  = lane & 8;

    float acc[4][4][4];
#pragma unroll
    for (int i = 0; i < 4; i++)
#pragma unroll
        for (int j = 0; j < 4; j++)
#pragma unroll
            for (int k = 0; k < 4; k++) acc[i][j][k] = 0.0f;

    // -------- direct load of chunk 0 (LDG+convert+STS) --------
    {
        const int k0 = 0;
        char* ah = smem + AHOF(0) + lm * PITCH + lkq * 2;
        char* al = smem + ALOF(0) + lm * PITCH + lkq * 2;
        if (PHASE1) {
            int tok = s_tok[lm];
            const float* src = x + (size_t)(tok < 0 ? 0 : tok) * DDIM + k0 + lkq;
#pragma unroll
            for (int j = 0; j < 4; j++) {
                float4 v = make_float4(0.f, 0.f, 0.f, 0.f);
                if (tok >= 0) v = *(const float4*)(src + j * 4);
                __nv_bfloat16 h0, h1, h2, h3, l0, l1, l2, l3;
                split_bf(v.x, h0, l0); split_bf(v.y, h1, l1);
                split_bf(v.z, h2, l2); split_bf(v.w, h3, l3);
                *(uint2*)(ah + j * 8) = make_uint2(pk(h0, h1), pk(h2, h3));
                *(uint2*)(al + j * 8) = make_uint2(pk(l0, l1), pk(l2, l3));
            }
        } else {
            size_t src = (size_t)(row0 + lm) * HDIM + k0 + lkq;
            *(uint4*)(ah)      = *(const uint4*)(g_hidden_hi + src);
            *(uint4*)(ah + 16) = *(const uint4*)(g_hidden_hi + src + 8);
            *(uint4*)(al)      = *(const uint4*)(g_hidden_lo + src);
            *(uint4*)(al + 16) = *(const uint4*)(g_hidden_lo + src + 8);
        }
        const float* wsrc = W + (size_t)(k0 + lbk) * ND + n0 + lbn;
        char* bh = smem + BHOF(0) + lbn * PITCH + lbk * 2;
        char* bl = smem + BLOF(0) + lbn * PITCH + lbk * 2;
#pragma unroll
        for (int j = 0; j < 4; j++) {
            float f0 = wsrc[(size_t)(4 * j + 0) * ND];
            float f1 = wsrc[(size_t)(4 * j + 1) * ND];
            float f2 = wsrc[(size_t)(4 * j + 2) * ND];
            float f3 = wsrc[(size_t)(4 * j + 3) * ND];
            __nv_bfloat16 h0, h1, h2, h3, l0, l1, l2, l3;
            split_bf(f0, h0, l0); split_bf(f1, h1, l1);
            split_bf(f2, h2, l2); split_bf(f3, h3, l3);
            *(uint2*)(bh + j * 8) = make_uint2(pk(h0, h1), pk(h2, h3));
            *(uint2*)(bl + j * 8) = make_uint2(pk(l0, l1), pk(l2, l3));
        }
    }
    __syncthreads();

    // -------- main loop: register-staged prefetch of c+1, compute c --------
    for (int c = 0; c < NC; c++) {
        const int buf = c & 1;
        const bool have = (c + 1 < NC);
        const int k0n = (c + 1) * KC;

        float4 stAf[4];     // phase1 A staging (fp32)
        uint4  stAu[4];     // phase2 A staging (bf16 hi/lo pairs)
        float  stB[16];
        if (have) {
            if (PHASE1) {
                int tok = s_tok[lm];
                const float* src = x + (size_t)(tok < 0 ? 0 : tok) * DDIM + k0n + lkq;
#pragma unroll
                for (int j = 0; j < 4; j++)
                    stAf[j] = (tok >= 0) ? *(const float4*)(src + j * 4)
                                         : make_float4(0.f, 0.f, 0.f, 0.f);
            } else {
                size_t src = (size_t)(row0 + lm) * HDIM + k0n + lkq;
                stAu[0] = *(const uint4*)(g_hidden_hi + src);
                stAu[1] = *(const uint4*)(g_hidden_hi + src + 8);
                stAu[2] = *(const uint4*)(g_hidden_lo + src);
                stAu[3] = *(const uint4*)(g_hidden_lo + src + 8);
            }
            const float* wsrc = W + (size_t)(k0n + lbk) * ND + n0 + lbn;
#pragma unroll
            for (int j = 0; j < 16; j++)
                stB[j] = wsrc[(size_t)j * ND];
        }

        // ---- compute on buffer `buf` ----
        {
            const uint32_t ahb = sb + AHOF(buf), alb = sb + ALOF(buf);
            const uint32_t bhb = sb + BHOF(buf), blb = sb + BLOF(buf);
#pragma unroll
            for (int ks = 0; ks < 2; ks++) {
                const int kk = ks * 16;
                const uint32_t baddr = (uint32_t)(b_row * PITCH + (kk + b_c8) * 2);
                const uint32_t aaddr = (uint32_t)(a_row * PITCH + (kk + a_c8) * 2);
                uint32_t b0[4], b1[4];
                // pass group 1: B_hi with A_hi and A_lo
                ldsm4(b0, bhb + baddr);
                ldsm4(b1, bhb + baddr + 16 * PITCH);
#pragma unroll
                for (int mi = 0; mi < 4; mi++) {
                    uint32_t af[4];
                    ldsm4(af, ahb + aaddr + mi * 16 * PITCH);
                    mma16816(acc[mi][0], af, b0); mma16816(acc[mi][1], af, b0 + 2);
                    mma16816(acc[mi][2], af, b1); mma16816(acc[mi][3], af, b1 + 2);
                    ldsm4(af, alb + aaddr + mi * 16 * PITCH);
                    mma16816(acc[mi][0], af, b0); mma16816(acc[mi][1], af, b0 + 2);
                    mma16816(acc[mi][2], af, b1); mma16816(acc[mi][3], af, b1 + 2);
                }
                // pass group 2: B_lo with A_hi
                ldsm4(b0, blb + baddr);
                ldsm4(b1, blb + baddr + 16 * PITCH);
#pragma unroll
                for (int mi = 0; mi < 4; mi++) {
                    uint32_t af[4];
                    ldsm4(af, ahb + aaddr + mi * 16 * PITCH);
                    mma16816(acc[mi][0], af, b0); mma16816(acc[mi][1], af, b0 + 2);
                    mma16816(acc[mi][2], af, b1); mma16816(acc[mi][3], af, b1 + 2);
                }
            }
        }

        // ---- convert + STS staged chunk into other buffer ----
        if (have) {
            const int nb = (c + 1) & 1;
            char* ah = smem + AHOF(nb) + lm * PITCH + lkq * 2;
            char* al = smem + ALOF(nb) + lm * PITCH + lkq * 2;
            if (PHASE1) {
#pragma unroll
                for (int j = 0; j < 4; j++) {
                    __nv_bfloat16 h0, h1, h2, h3, l0, l1, l2, l3;
                    split_bf(stAf[j].x, h0, l0); split_bf(stAf[j].y, h1, l1);
                    split_bf(stAf[j].z, h2, l2); split_bf(stAf[j].w, h3, l3);
                    *(uint2*)(ah + j * 8) = make_uint2(pk(h0, h1), pk(h2, h3));
                    *(uint2*)(al + j * 8) = make_uint2(pk(l0, l1), pk(l2, l3));
                }
            } else {
                *(uint4*)(ah)      = stAu[0];
                *(uint4*)(ah + 16) = stAu[1];
                *(uint4*)(al)      = stAu[2];
                *(uint4*)(al + 16) = stAu[3];
            }
            char* bh = smem + BHOF(nb) + lbn * PITCH + lbk * 2;
            char* bl = smem + BLOF(nb) + lbn * PITCH + lbk * 2;
#pragma unroll
            for (int j = 0; j < 4; j++) {
                __nv_bfloat16 h0, h1, h2, h3, l0, l1, l2, l3;
                split_bf(stB[4 * j + 0], h0, l0); split_bf(stB[4 * j + 1], h1, l1);
                split_bf(stB[4 * j + 2], h2, l2); split_bf(stB[4 * j + 3], h3, l3);
                *(uint2*)(bh + j * 8) = make_uint2(pk(h0, h1), pk(h2, h3));
                *(uint2*)(bl + j * 8) = make_uint2(pk(l0, l1), pk(l2, l3));
            }
        }
        __syncthreads();
    }

    // -------- epilogue --------
    const int gid = lane >> 2, tig = lane & 3;
#pragma unroll
    for (int mi = 0; mi < 4; mi++) {
#pragma unroll
        for (int f = 0; f < 4; f++) {
            const int c = n0 + warp_n + f * 8 + tig * 2;
#pragma unroll
            for (int h = 0; h < 2; h++) {
                const int r = warp_m + mi * 16 + gid + h * 8;
                float v0 = acc[mi][f][2 * h];
                float v1 = acc[mi][f][2 * h + 1];
                if (PHASE1) {
                    v0 = v0 / (1.0f + __expf(-v0));
                    v1 = v1 / (1.0f + __expf(-v1));
                    __nv_bfloat16 h0, h1, l0, l1;
                    split_bf(v0, h0, l0); split_bf(v1, h1, l1);
                    size_t off = (size_t)(row0 + r) * HDIM + c;
                    *(uint32_t*)(g_hidden_hi + off) = pk(h0, h1);
                    *(uint32_t*)(g_hidden_lo + off) = pk(l0, l1);
                } else {
                    int tok = s_tok[r];
                    if (tok >= 0) {
                        float w = s_w[r];
                        float* op = out + (size_t)tok * DDIM + c;
                        atomicAdd(op,     w * v0);
                        atomicAdd(op + 1, w * v1);
                    }
                }
            }
        }
    }
}

// ---------------- launch ----------------
extern "C" void kernel_launch(void* const* d_in, const int* in_sizes, int n_in,
                              void* d_out, int out_size) {
    const float* x   = (const float*)d_in[0];
    const float* gw  = (const float*)d_in[1];
    const float* sw1 = (const float*)d_in[2];
    const float* sw2 = (const float*)d_in[3];
    const float* ew1 = (const float*)d_in[4];
    const float* ew2 = (const float*)d_in[5];
    float* out = (float*)d_out;

    cudaFuncSetAttribute(ffn_mma<true>,  cudaFuncAttributeMaxDynamicSharedMemorySize, SMEM_BYTES);
    cudaFuncSetAttribute(ffn_mma<false>, cudaFuncAttributeMaxDynamicSharedMemorySize, SMEM_BYTES);

    init_kernel<<<1024, 256>>>(out);
    router_kernel<<<NTOK, 128>>>(x, gw);
    schedule_kernel<<<1, 32>>>(out, (long long)out_size);
    scatter_kernel<<<(NTOK * (TOPK + NS) + 255) / 256, 256>>>();

    dim3 g1(MAXTILESM, HDIM / TN);   // 144 x 11
    dim3 g2(MAXTILESM, DDIM / TN);   // 144 x 16
    ffn_mma<true ><<<g1, 256, SMEM_BYTES>>>(x, sw1, sw2, ew1, ew2, out);
    ffn_mma<false><<<g2, 256, SMEM_BYTES>>>(x, sw1, sw2, ew1, ew2, out);
}